// round 13
// baseline (speedup 1.0000x reference)
#include <cuda_runtime.h>
#include <math.h>

#define Bc   2
#define Hc   16
#define Nc   8192
#define Dc   64
#define BHc  (Bc*Hc)
#define NBc  (Nc/256)     // 32 blocks per (b,h)
#define Sc   256          // sample size
#define Pc   7            // LSH projections

// ---- scratch (device globals: no runtime allocation allowed) ----
__device__ int g_qhash[BHc*Nc];
__device__ int g_khash[BHc*Nc];
__device__ int g_qidx [BHc*Nc];
__device__ int g_kidx [BHc*Nc];

typedef unsigned long long ull;

// ---- packed f32x2 helpers (sm_103a FFMA2 path, PTX-only) ----
__device__ __forceinline__ ull ffma2(ull a, ull b, ull c) {
    ull d; asm("fma.rn.f32x2 %0,%1,%2,%3;" : "=l"(d) : "l"(a), "l"(b), "l"(c)); return d;
}
__device__ __forceinline__ ull fadd2(ull a, ull b) {
    ull d; asm("add.rn.f32x2 %0,%1,%2;" : "=l"(d) : "l"(a), "l"(b)); return d;
}
__device__ __forceinline__ ull fmul2(ull a, ull b) {
    ull d; asm("mul.rn.f32x2 %0,%1,%2;" : "=l"(d) : "l"(a), "l"(b)); return d;
}
__device__ __forceinline__ ull pack2(float lo, float hi) {
    ull r; asm("mov.b64 %0,{%1,%2};" : "=l"(r) : "f"(lo), "f"(hi)); return r;
}
__device__ __forceinline__ float2 unpack2(ull v) {
    float lo, hi; asm("mov.b64 {%0,%1},%2;" : "=f"(lo), "=f"(hi) : "l"(v));
    return make_float2(lo, hi);
}

// ============================================================
// Kernel A: LSH hash for query and key rows.
// bucket = gray(code) = code ^ (code>>1), code = sum_r (proj_r > 0) << r
// Row loads vectorized (16x LDG.128); FMA accumulation order kept
// bit-identical to the previous passing kernel (ascending d per r).
// ============================================================
__global__ void hash_kernel(const float* __restrict__ q,
                            const float* __restrict__ k,
                            const float* __restrict__ pd) {
    __shared__ float spd[Dc*Pc];
    int tid = threadIdx.x;
    for (int i = tid; i < Dc*Pc; i += blockDim.x) spd[i] = pd[i];
    __syncthreads();

    int gid   = blockIdx.x * blockDim.x + tid;
    int total = BHc*Nc;
    bool isK  = gid >= total;
    int idx   = isK ? gid - total : gid;
    const float4* row4 = (const float4*)((isK ? k : q) + (size_t)idx * Dc);

    float4 x[16];
#pragma unroll
    for (int i = 0; i < 16; i++) x[i] = row4[i];   // batched, MLP=16

    float s[Pc];
#pragma unroll
    for (int r = 0; r < Pc; r++) s[r] = 0.f;
#pragma unroll
    for (int d4 = 0; d4 < 16; d4++) {
        float4 xv = x[d4];
        // identical arithmetic to scalar version: per r, ascending-d fma chain
#pragma unroll
        for (int r = 0; r < Pc; r++) s[r] = fmaf(xv.x, spd[(4*d4+0)*Pc + r], s[r]);
#pragma unroll
        for (int r = 0; r < Pc; r++) s[r] = fmaf(xv.y, spd[(4*d4+1)*Pc + r], s[r]);
#pragma unroll
        for (int r = 0; r < Pc; r++) s[r] = fmaf(xv.z, spd[(4*d4+2)*Pc + r], s[r]);
#pragma unroll
        for (int r = 0; r < Pc; r++) s[r] = fmaf(xv.w, spd[(4*d4+3)*Pc + r], s[r]);
    }
    int code = 0;
#pragma unroll
    for (int r = 0; r < Pc; r++) code |= (s[r] > 0.f) << r;
    int bucket = code ^ (code >> 1);
    (isK ? g_khash : g_qhash)[idx] = bucket;
}

// ============================================================
// Kernel B: stable counting sort (ascending) of 8192 keys in [0,128)
// ============================================================
__global__ void sort_kernel() {
    __shared__ int sh[Nc];
    __shared__ int cnt[128];
    __shared__ int start[128];
    int bh  = blockIdx.x;
    bool isK = blockIdx.y != 0;
    const int* hash = (isK ? g_khash : g_qhash) + bh*Nc;
    int*       idx  = (isK ? g_kidx  : g_qidx ) + bh*Nc;
    int tid = threadIdx.x;  // 128 threads

    cnt[tid] = 0;
    __syncthreads();
    for (int i = tid; i < Nc; i += 128) {
        int v = hash[i];
        sh[i] = v;
        atomicAdd(&cnt[v], 1);
    }
    __syncthreads();
    if (tid == 0) {
        int run = 0;
        for (int t = 0; t < 128; t++) { start[t] = run; run += cnt[t]; }
    }
    __syncthreads();
    int off = start[tid];
    for (int i = 0; i < Nc; i++)
        if (sh[i] == tid) idx[off++] = i;
}

// ============================================================
// Kernel C (fused): block-diagonal attention + sampled residual +
// linear combine + un-sort scatter, one CTA per (block, bh).
//
// Split-row layout: 512 threads, thread = (row = tid>>1, half = tid&1).
// Each thread owns 32 of the 64 dims of its query row (qp[16] ull) and
// 32 dims of the output accumulator (ap[16] ull) -> ~110 regs, one
// 16-warp CTA per SM (4 warps/SMSP) instead of 8 warps.
// Partial dot exchanged within the lane pair via shfl_xor(1); fp add is
// commutative so both lanes compute bit-identical s, p, l.
//
// Linear-combine identity (unchanged):
//   out = (acc_blk + C*acc_res) / (l_blk + C*l_res),
//   C = (N-256)/sampled_cnt.  Raw expf never overflows (|s| small).
// ============================================================
__global__ void __launch_bounds__(512, 1)
attn_kernel(const float* __restrict__ q,
            const float* __restrict__ k,
            const float* __restrict__ v,
            const int* __restrict__ sampled,
            float* __restrict__ out) {
    extern __shared__ float sm[];
    float* Ks = sm;
    float* Vs = sm + 256*Dc;
    __shared__ int smask[Sc];
    int blk = blockIdx.x, bh = blockIdx.y;
    int tid  = threadIdx.x;
    int row  = tid >> 1;
    int half = tid & 1;
    size_t bhN = (size_t)bh * Nc;

    // sampled-set mask (uniform per chunk: row block == sample's block)
    int myms = 0;
    if (tid < Sc) {
        int sv = sampled[bh*Sc + tid];
        myms = ((sv >> 8) == blk) ? 1 : 0;
        smask[tid] = myms;
    }
    int cnt = __syncthreads_count(myms);
    float C = (cnt < Sc) ? (float)(Nc - 256) / (float)(Sc - cnt) : 0.f;

    int ssrow = sampled[bh*Sc + row];   // sampled row for phase-2 staging

    // ---- stage block K/V tile (each thread loads half a row) ----
    {
        int kidx = g_kidx[bh*Nc + blk*256 + row];
        const float4* kr = (const float4*)(k + (bhN + kidx)*Dc) + half*8;
        const float4* vr = (const float4*)(v + (bhN + kidx)*Dc) + half*8;
        float4* Ks4 = (float4*)(Ks + row*Dc + half*32);
        float4* Vs4 = (float4*)(Vs + row*Dc + half*32);
#pragma unroll
        for (int i = 0; i < 8; i++) { Ks4[i] = kr[i]; Vs4[i] = vr[i]; }
    }
    __syncthreads();

    // ---- per-thread half query row (packed f32x2) ----
    int qidx = g_qidx[bh*Nc + blk*256 + row];
    ull qp[16];
    {
        const ulonglong2* qr = (const ulonglong2*)(q + (bhN + qidx)*Dc + half*32);
#pragma unroll
        for (int i = 0; i < 8; i++) { ulonglong2 t = qr[i]; qp[2*i] = t.x; qp[2*i+1] = t.y; }
    }
    ull ap[16];
#pragma unroll
    for (int i = 0; i < 16; i++) ap[i] = 0ull;
    float l = 0.f;

    // ---- phase 1: block-diagonal attention (weight 1) ----
    for (int j = 0; j < 256; j++) {
        const ulonglong2* kj = (const ulonglong2*)(Ks + j*Dc + half*32);
        ull s0 = 0ull, s1 = 0ull, s2 = 0ull, s3 = 0ull;
#pragma unroll
        for (int i = 0; i < 8; i += 2) {
            ulonglong2 t0 = kj[i], t1 = kj[i+1];
            s0 = ffma2(qp[2*i  ], t0.x, s0);
            s1 = ffma2(qp[2*i+1], t0.y, s1);
            s2 = ffma2(qp[2*i+2], t1.x, s2);
            s3 = ffma2(qp[2*i+3], t1.y, s3);
        }
        float2 sv = unpack2(fadd2(fadd2(s0, s1), fadd2(s2, s3)));
        float part  = sv.x + sv.y;
        float other = __shfl_xor_sync(0xffffffffu, part, 1);
        float p = __expf((part + other) * 0.125f);
        l += p;
        ull pp = pack2(p, p);
        const ulonglong2* vj = (const ulonglong2*)(Vs + j*Dc + half*32);
#pragma unroll
        for (int i = 0; i < 8; i++) {
            ulonglong2 t = vj[i];
            ap[2*i  ] = ffma2(pp, t.x, ap[2*i  ]);
            ap[2*i+1] = ffma2(pp, t.y, ap[2*i+1]);
        }
    }

    // ---- re-stage smem with sampled K/V tile ----
    __syncthreads();
    {
        int kidx = g_kidx[bh*Nc + ssrow];
        const float4* kr = (const float4*)(k + (bhN + kidx)*Dc) + half*8;
        const float4* vr = (const float4*)(v + (bhN + kidx)*Dc) + half*8;
        float4* Ks4 = (float4*)(Ks + row*Dc + half*32);
        float4* Vs4 = (float4*)(Vs + row*Dc + half*32);
#pragma unroll
        for (int i = 0; i < 8; i++) { Ks4[i] = kr[i]; Vs4[i] = vr[i]; }
    }
    __syncthreads();

    // ---- phase 2: sampled residual (weight C, skip in-block cols) ----
    for (int j = 0; j < Sc; j++) {
        if (smask[j]) continue;           // uniform branch across CTA
        const ulonglong2* kj = (const ulonglong2*)(Ks + j*Dc + half*32);
        ull s0 = 0ull, s1 = 0ull, s2 = 0ull, s3 = 0ull;
#pragma unroll
        for (int i = 0; i < 8; i += 2) {
            ulonglong2 t0 = kj[i], t1 = kj[i+1];
            s0 = ffma2(qp[2*i  ], t0.x, s0);
            s1 = ffma2(qp[2*i+1], t0.y, s1);
            s2 = ffma2(qp[2*i+2], t1.x, s2);
            s3 = ffma2(qp[2*i+3], t1.y, s3);
        }
        float2 sv = unpack2(fadd2(fadd2(s0, s1), fadd2(s2, s3)));
        float part  = sv.x + sv.y;
        float other = __shfl_xor_sync(0xffffffffu, part, 1);
        float p = C * __expf((part + other) * 0.125f);
        l += p;
        ull pp = pack2(p, p);
        const ulonglong2* vj = (const ulonglong2*)(Vs + j*Dc + half*32);
#pragma unroll
        for (int i = 0; i < 8; i++) {
            ulonglong2 t = vj[i];
            ap[2*i  ] = ffma2(pp, t.x, ap[2*i  ]);
            ap[2*i+1] = ffma2(pp, t.y, ap[2*i+1]);
        }
    }

    // ---- normalize + un-sort scatter (half row each) ----
    float inv = 1.f / l;
    ull iv = pack2(inv, inv);
    ulonglong2* o2 = (ulonglong2*)(out + (bhN + qidx)*Dc + half*32);
#pragma unroll
    for (int i = 0; i < 8; i++) {
        ulonglong2 t;
        t.x = fmul2(ap[2*i  ], iv);
        t.y = fmul2(ap[2*i+1], iv);
        o2[i] = t;
    }
}

// ============================================================
extern "C" void kernel_launch(void* const* d_in, const int* in_sizes, int n_in,
                              void* d_out, int out_size) {
    const float* q  = (const float*)d_in[0];
    const float* k  = (const float*)d_in[1];
    const float* v  = (const float*)d_in[2];
    const float* pd = (const float*)d_in[3];
    const int* sampled = (const int*)d_in[4];
    float* out = (float*)d_out;

    constexpr size_t SMEM_C = (size_t)2 * 256 * Dc * sizeof(float);  // 128 KB
    cudaFuncSetAttribute(attn_kernel, cudaFuncAttributeMaxDynamicSharedMemorySize, (int)SMEM_C);

    hash_kernel<<<(2*BHc*Nc)/256, 256>>>(q, k, pd);
    sort_kernel<<<dim3(BHc, 2), 128>>>();
    attn_kernel<<<dim3(NBc, BHc), 512, SMEM_C>>>(q, k, v, sampled, out);
}

// round 14
// speedup vs baseline: 1.6873x; 1.6873x over previous
#include <cuda_runtime.h>
#include <math.h>

#define Bc   2
#define Hc   16
#define Nc   8192
#define Dc   64
#define BHc  (Bc*Hc)
#define NBc  (Nc/256)     // 32 blocks per (b,h)
#define Sc   256          // sample size
#define Pc   7            // LSH projections

// ---- scratch (device globals: no runtime allocation allowed) ----
__device__ int g_qhash[BHc*Nc];
__device__ int g_khash[BHc*Nc];
__device__ int g_qidx [BHc*Nc];
__device__ int g_kidx [BHc*Nc];

typedef unsigned long long ull;

// ---- packed f32x2 helpers (sm_103a FFMA2 path, PTX-only) ----
__device__ __forceinline__ ull ffma2(ull a, ull b, ull c) {
    ull d; asm("fma.rn.f32x2 %0,%1,%2,%3;" : "=l"(d) : "l"(a), "l"(b), "l"(c)); return d;
}
__device__ __forceinline__ ull fadd2(ull a, ull b) {
    ull d; asm("add.rn.f32x2 %0,%1,%2;" : "=l"(d) : "l"(a), "l"(b)); return d;
}
__device__ __forceinline__ ull fmul2(ull a, ull b) {
    ull d; asm("mul.rn.f32x2 %0,%1,%2;" : "=l"(d) : "l"(a), "l"(b)); return d;
}
__device__ __forceinline__ ull pack2(float lo, float hi) {
    ull r; asm("mov.b64 %0,{%1,%2};" : "=l"(r) : "f"(lo), "f"(hi)); return r;
}
__device__ __forceinline__ float2 unpack2(ull v) {
    float lo, hi; asm("mov.b64 {%0,%1},%2;" : "=f"(lo), "=f"(hi) : "l"(v));
    return make_float2(lo, hi);
}

// ============================================================
// Kernel A: LSH hash for query and key rows (vectorized loads).
// bucket = gray(code) = code ^ (code>>1), code = sum_r (proj_r > 0) << r
// ============================================================
__global__ void hash_kernel(const float* __restrict__ q,
                            const float* __restrict__ k,
                            const float* __restrict__ pd) {
    __shared__ float spd[Dc*Pc];
    int tid = threadIdx.x;
    for (int i = tid; i < Dc*Pc; i += blockDim.x) spd[i] = pd[i];
    __syncthreads();

    int gid   = blockIdx.x * blockDim.x + tid;
    int total = BHc*Nc;
    bool isK  = gid >= total;
    int idx   = isK ? gid - total : gid;
    const float4* row4 = (const float4*)((isK ? k : q) + (size_t)idx * Dc);

    float4 x[16];
#pragma unroll
    for (int i = 0; i < 16; i++) x[i] = row4[i];   // batched, MLP=16

    float s[Pc];
#pragma unroll
    for (int r = 0; r < Pc; r++) s[r] = 0.f;
#pragma unroll
    for (int d4 = 0; d4 < 16; d4++) {
        float4 xv = x[d4];
#pragma unroll
        for (int r = 0; r < Pc; r++) s[r] = fmaf(xv.x, spd[(4*d4+0)*Pc + r], s[r]);
#pragma unroll
        for (int r = 0; r < Pc; r++) s[r] = fmaf(xv.y, spd[(4*d4+1)*Pc + r], s[r]);
#pragma unroll
        for (int r = 0; r < Pc; r++) s[r] = fmaf(xv.z, spd[(4*d4+2)*Pc + r], s[r]);
#pragma unroll
        for (int r = 0; r < Pc; r++) s[r] = fmaf(xv.w, spd[(4*d4+3)*Pc + r], s[r]);
    }
    int code = 0;
#pragma unroll
    for (int r = 0; r < Pc; r++) code |= (s[r] > 0.f) << r;
    int bucket = code ^ (code >> 1);
    (isK ? g_khash : g_qhash)[idx] = bucket;
}

// ============================================================
// Kernel B: stable counting sort (ascending) of 8192 keys in [0,128)
// ============================================================
__global__ void sort_kernel() {
    __shared__ int sh[Nc];
    __shared__ int cnt[128];
    __shared__ int start[128];
    int bh  = blockIdx.x;
    bool isK = blockIdx.y != 0;
    const int* hash = (isK ? g_khash : g_qhash) + bh*Nc;
    int*       idx  = (isK ? g_kidx  : g_qidx ) + bh*Nc;
    int tid = threadIdx.x;  // 128 threads

    cnt[tid] = 0;
    __syncthreads();
    for (int i = tid; i < Nc; i += 128) {
        int v = hash[i];
        sh[i] = v;
        atomicAdd(&cnt[v], 1);
    }
    __syncthreads();
    if (tid == 0) {
        int run = 0;
        for (int t = 0; t < 128; t++) { start[t] = run; run += cnt[t]; }
    }
    __syncthreads();
    int off = start[tid];
    for (int i = 0; i < Nc; i++)
        if (sh[i] == tid) idx[off++] = i;
}

// ============================================================
// Kernel C (fused): block-diagonal attention + sampled residual +
// linear combine + un-sort scatter. One CTA per (block, bh),
// 256 threads, one query row per thread (R9 layout), j unrolled x2
// for ILP (8 independent dot accumulators, 2 exps in flight).
//
// Linear-combine identity:
//   out = (acc_blk + C*acc_res) / (l_blk + C*l_res),
//   C = (N-256)/sampled_cnt.  Raw expf never overflows (|s| small).
// Phase-2 mask handled by predicated p=0 (adds exact zeros).
// ============================================================
__global__ void __launch_bounds__(256, 1)
attn_kernel(const float* __restrict__ q,
            const float* __restrict__ k,
            const float* __restrict__ v,
            const int* __restrict__ sampled,
            float* __restrict__ out) {
    extern __shared__ float sm[];
    float* Ks = sm;
    float* Vs = sm + 256*Dc;
    __shared__ int smask[Sc];
    int blk = blockIdx.x, bh = blockIdx.y;
    int tid = threadIdx.x;
    size_t bhN = (size_t)bh * Nc;

    // sampled-set mask (uniform per chunk: row block == sample's block)
    int ss  = sampled[bh*Sc + tid];
    int msk = ((ss >> 8) == blk) ? 1 : 0;
    smask[tid] = msk;
    int cnt = __syncthreads_count(msk);
    float C = (cnt < Sc) ? (float)(Nc - 256) / (float)(Sc - cnt) : 0.f;

    // ---- stage block K/V tile ----
    {
        int kidx = g_kidx[bh*Nc + blk*256 + tid];
        const float4* kr = (const float4*)(k + (bhN + kidx)*Dc);
        const float4* vr = (const float4*)(v + (bhN + kidx)*Dc);
        float4* Ks4 = (float4*)(Ks + tid*Dc);
        float4* Vs4 = (float4*)(Vs + tid*Dc);
#pragma unroll
        for (int i = 0; i < 16; i++) { Ks4[i] = kr[i]; Vs4[i] = vr[i]; }
    }
    __syncthreads();

    // ---- per-thread query row (packed f32x2) ----
    int qidx = g_qidx[bh*Nc + blk*256 + tid];
    ull qp[32];
    {
        const ulonglong2* qr = (const ulonglong2*)(q + (bhN + qidx)*Dc);
#pragma unroll
        for (int i = 0; i < 16; i++) { ulonglong2 t = qr[i]; qp[2*i] = t.x; qp[2*i+1] = t.y; }
    }
    ull ap[32];
#pragma unroll
    for (int i = 0; i < 32; i++) ap[i] = 0ull;
    float l = 0.f;

    // ---- phase 1: block-diagonal attention (weight 1), j unrolled x2 ----
    for (int j = 0; j < 256; j += 2) {
        const ulonglong2* kja = (const ulonglong2*)(Ks + j*Dc);
        const ulonglong2* kjb = (const ulonglong2*)(Ks + (j+1)*Dc);
        ull a0 = 0ull, a1 = 0ull, a2 = 0ull, a3 = 0ull;
        ull b0 = 0ull, b1 = 0ull, b2 = 0ull, b3 = 0ull;
#pragma unroll
        for (int i = 0; i < 16; i += 2) {
            ulonglong2 ta0 = kja[i], ta1 = kja[i+1];
            ulonglong2 tb0 = kjb[i], tb1 = kjb[i+1];
            a0 = ffma2(qp[2*i  ], ta0.x, a0);
            a1 = ffma2(qp[2*i+1], ta0.y, a1);
            a2 = ffma2(qp[2*i+2], ta1.x, a2);
            a3 = ffma2(qp[2*i+3], ta1.y, a3);
            b0 = ffma2(qp[2*i  ], tb0.x, b0);
            b1 = ffma2(qp[2*i+1], tb0.y, b1);
            b2 = ffma2(qp[2*i+2], tb1.x, b2);
            b3 = ffma2(qp[2*i+3], tb1.y, b3);
        }
        float2 sa = unpack2(fadd2(fadd2(a0, a1), fadd2(a2, a3)));
        float2 sb = unpack2(fadd2(fadd2(b0, b1), fadd2(b2, b3)));
        float pa = __expf((sa.x + sa.y) * 0.125f);
        float pb = __expf((sb.x + sb.y) * 0.125f);
        l += pa; l += pb;
        ull ppa = pack2(pa, pa);
        ull ppb = pack2(pb, pb);
        const ulonglong2* vja = (const ulonglong2*)(Vs + j*Dc);
        const ulonglong2* vjb = (const ulonglong2*)(Vs + (j+1)*Dc);
#pragma unroll
        for (int i = 0; i < 16; i++) {
            ulonglong2 ta = vja[i];
            ulonglong2 tb = vjb[i];
            ap[2*i  ] = ffma2(ppa, ta.x, ap[2*i  ]);
            ap[2*i+1] = ffma2(ppa, ta.y, ap[2*i+1]);
            ap[2*i  ] = ffma2(ppb, tb.x, ap[2*i  ]);
            ap[2*i+1] = ffma2(ppb, tb.y, ap[2*i+1]);
        }
    }

    // ---- re-stage smem with sampled K/V tile ----
    __syncthreads();
    {
        int kidx = g_kidx[bh*Nc + ss];
        const float4* kr = (const float4*)(k + (bhN + kidx)*Dc);
        const float4* vr = (const float4*)(v + (bhN + kidx)*Dc);
        float4* Ks4 = (float4*)(Ks + tid*Dc);
        float4* Vs4 = (float4*)(Vs + tid*Dc);
#pragma unroll
        for (int i = 0; i < 16; i++) { Ks4[i] = kr[i]; Vs4[i] = vr[i]; }
    }
    __syncthreads();

    // ---- phase 2: sampled residual (weight C, masked cols -> p=0) ----
    for (int j = 0; j < Sc; j += 2) {
        const ulonglong2* kja = (const ulonglong2*)(Ks + j*Dc);
        const ulonglong2* kjb = (const ulonglong2*)(Ks + (j+1)*Dc);
        ull a0 = 0ull, a1 = 0ull, a2 = 0ull, a3 = 0ull;
        ull b0 = 0ull, b1 = 0ull, b2 = 0ull, b3 = 0ull;
#pragma unroll
        for (int i = 0; i < 16; i += 2) {
            ulonglong2 ta0 = kja[i], ta1 = kja[i+1];
            ulonglong2 tb0 = kjb[i], tb1 = kjb[i+1];
            a0 = ffma2(qp[2*i  ], ta0.x, a0);
            a1 = ffma2(qp[2*i+1], ta0.y, a1);
            a2 = ffma2(qp[2*i+2], ta1.x, a2);
            a3 = ffma2(qp[2*i+3], ta1.y, a3);
            b0 = ffma2(qp[2*i  ], tb0.x, b0);
            b1 = ffma2(qp[2*i+1], tb0.y, b1);
            b2 = ffma2(qp[2*i+2], tb1.x, b2);
            b3 = ffma2(qp[2*i+3], tb1.y, b3);
        }
        float2 sa = unpack2(fadd2(fadd2(a0, a1), fadd2(a2, a3)));
        float2 sb = unpack2(fadd2(fadd2(b0, b1), fadd2(b2, b3)));
        float pa = smask[j]   ? 0.f : C * __expf((sa.x + sa.y) * 0.125f);
        float pb = smask[j+1] ? 0.f : C * __expf((sb.x + sb.y) * 0.125f);
        l += pa; l += pb;
        ull ppa = pack2(pa, pa);
        ull ppb = pack2(pb, pb);
        const ulonglong2* vja = (const ulonglong2*)(Vs + j*Dc);
        const ulonglong2* vjb = (const ulonglong2*)(Vs + (j+1)*Dc);
#pragma unroll
        for (int i = 0; i < 16; i++) {
            ulonglong2 ta = vja[i];
            ulonglong2 tb = vjb[i];
            ap[2*i  ] = ffma2(ppa, ta.x, ap[2*i  ]);
            ap[2*i+1] = ffma2(ppa, ta.y, ap[2*i+1]);
            ap[2*i  ] = ffma2(ppb, tb.x, ap[2*i  ]);
            ap[2*i+1] = ffma2(ppb, tb.y, ap[2*i+1]);
        }
    }

    // ---- normalize + un-sort scatter ----
    float inv = 1.f / l;
    ull iv = pack2(inv, inv);
    ulonglong2* o2 = (ulonglong2*)(out + (bhN + qidx)*Dc);
#pragma unroll
    for (int i = 0; i < 16; i++) {
        ulonglong2 t;
        t.x = fmul2(ap[2*i  ], iv);
        t.y = fmul2(ap[2*i+1], iv);
        o2[i] = t;
    }
}

// ============================================================
extern "C" void kernel_launch(void* const* d_in, const int* in_sizes, int n_in,
                              void* d_out, int out_size) {
    const float* q  = (const float*)d_in[0];
    const float* k  = (const float*)d_in[1];
    const float* v  = (const float*)d_in[2];
    const float* pd = (const float*)d_in[3];
    const int* sampled = (const int*)d_in[4];
    float* out = (float*)d_out;

    constexpr size_t SMEM_C = (size_t)2 * 256 * Dc * sizeof(float);  // 128 KB
    cudaFuncSetAttribute(attn_kernel, cudaFuncAttributeMaxDynamicSharedMemorySize, (int)SMEM_C);

    hash_kernel<<<(2*BHc*Nc)/256, 256>>>(q, k, pd);
    sort_kernel<<<dim3(BHc, 2), 128>>>();
    attn_kernel<<<dim3(NBc, BHc), 256, SMEM_C>>>(q, k, v, sampled, out);
}